// round 3
// baseline (speedup 1.0000x reference)
#include <cuda_runtime.h>
#include <cstdint>

// Problem constants (fixed by the dataset)
#define NMAX 100000
#define EMAX 800000
#define C 96            // IN_C
#define OC 64           // OUT_C
#define SCAN_B 1024
#define NB_MAX 128      // ceil(NMAX/1024) = 98

// ---- scratch (static device globals; no allocation at runtime) ----
__device__ int   g_ecount[NMAX];      // in-degree over real edges (excl. self loop)
__device__ int   g_cursor[NMAX];
__device__ int   g_csr_start[NMAX];
__device__ int   g_bsums[NB_MAX];
__device__ float g_dinv[NMAX];
__device__ int   g_csr_src[EMAX];
__device__ float g_y1[(size_t)NMAX * C];
__device__ float g_y2[(size_t)NMAX * C];

// ---------------------------------------------------------------- init
__global__ void k_init(int n) {
    int i = blockIdx.x * blockDim.x + threadIdx.x;
    if (i < n) { g_ecount[i] = 0; g_cursor[i] = 0; }
}

// ---------------------------------------------------------------- histogram over col
// edge_index arrives as int32 (JAX x64 disabled downcasts int64 -> int32)
__global__ void k_hist(const int* __restrict__ ei, int e) {
    int i = blockIdx.x * blockDim.x + threadIdx.x;
    if (i < e) {
        int col = ei[e + i];
        atomicAdd(&g_ecount[col], 1);
    }
}

// ---------------------------------------------------------------- block-level exclusive scan
__global__ void k_scan_blocks(int n) {
    __shared__ int s[SCAN_B];
    int tid = threadIdx.x;
    int i = blockIdx.x * SCAN_B + tid;
    int v = (i < n) ? g_ecount[i] : 0;
    s[tid] = v;
    __syncthreads();
    for (int off = 1; off < SCAN_B; off <<= 1) {
        int t = (tid >= off) ? s[tid - off] : 0;
        __syncthreads();
        s[tid] += t;
        __syncthreads();
    }
    if (i < n) g_csr_start[i] = s[tid] - v;   // exclusive
    if (tid == SCAN_B - 1) g_bsums[blockIdx.x] = s[SCAN_B - 1];
}

__global__ void k_scan_sums(int nb) {
    if (threadIdx.x == 0 && blockIdx.x == 0) {
        int run = 0;
        for (int i = 0; i < nb; i++) { int t = g_bsums[i]; g_bsums[i] = run; run += t; }
    }
}

__global__ void k_scan_fixup(int n) {
    int i = blockIdx.x * blockDim.x + threadIdx.x;
    if (i < n) {
        g_csr_start[i] += g_bsums[i >> 10];
        g_dinv[i] = rsqrtf((float)(g_ecount[i] + 1));   // deg includes self loop
    }
}

// ---------------------------------------------------------------- CSR fill (by destination)
__global__ void k_fill(const int* __restrict__ ei, int e) {
    int i = blockIdx.x * blockDim.x + threadIdx.x;
    if (i < e) {
        int src = ei[i];
        int col = ei[e + i];
        int pos = g_csr_start[col] + atomicAdd(&g_cursor[col], 1);
        g_csr_src[pos] = src;
    }
}

// ---------------------------------------------------------------- one propagation hop
// y[c] = dinv[c]^2 * x[c] + sum_{s in N_in(c)} dinv[s]*dinv[c]*x[s]
// pass 0: x_ext -> g_y1 ; pass 1: g_y1 -> g_y2
// one warp per destination node; lane covers channels {lane, lane+32, lane+64}
__global__ void k_hop(const float* __restrict__ x_ext, int pass, int n) {
    int warp = (blockIdx.x * blockDim.x + threadIdx.x) >> 5;
    int lane = threadIdx.x & 31;
    if (warp >= n) return;
    const float* __restrict__ xin = (pass == 0) ? x_ext : g_y1;
    float* __restrict__ yout      = (pass == 0) ? g_y1  : g_y2;

    int c = warp;
    float dc = g_dinv[c];
    const float* xr = xin + (size_t)c * C;
    float wl = dc * dc;
    float a0 = wl * xr[lane];
    float a1 = wl * xr[lane + 32];
    float a2 = wl * xr[lane + 64];

    int st  = g_csr_start[c];
    int cnt = g_ecount[c];
    int end = st + cnt;
    for (int k = st; k < end; k++) {
        int s   = g_csr_src[k];
        float w = dc * g_dinv[s];
        const float* xs = xin + (size_t)s * C;
        a0 += w * xs[lane];
        a1 += w * xs[lane + 32];
        a2 += w * xs[lane + 64];
    }
    float* yr = yout + (size_t)c * C;
    yr[lane]      = a0;
    yr[lane + 32] = a1;
    yr[lane + 64] = a2;
}

// ---------------------------------------------------------------- GEMM + bias + sigmoid
// out[n][oc] = sigmoid(b[oc] + sum_ic y2[n][ic] * W[oc][ic])
// block tile: 32 nodes x 64 oc, 256 threads
// thread (tx = t%16, ty = t/16): oc in {tx, tx+16, tx+32, tx+48}, nodes {ty*2, ty*2+1}
__global__ void k_gemm_sig(const float* __restrict__ Wm, const float* __restrict__ bias,
                           float* __restrict__ out, int n) {
    __shared__ float ws[OC][C + 1];       // pad 97 -> ws reads land on distinct banks
    __shared__ float xs[C][34];           // transposed x tile, pad 34 keeps float2 aligned
    __shared__ float bs[OC];

    int t = threadIdx.x;
    int node0 = blockIdx.x * 32;

    for (int i = t; i < OC * C; i += 256) {
        ws[i / C][i % C] = Wm[i];
    }
    if (t < OC) bs[t] = bias[t];
    for (int i = t; i < 32 * C; i += 256) {
        int nl = i / C, ic = i % C;
        int node = node0 + nl;
        xs[ic][nl] = (node < n) ? g_y2[(size_t)node * C + ic] : 0.0f;
    }
    __syncthreads();

    int tx = t & 15;
    int ty = t >> 4;

    float acc[2][4];
#pragma unroll
    for (int i = 0; i < 2; i++)
#pragma unroll
        for (int j = 0; j < 4; j++) acc[i][j] = 0.0f;

#pragma unroll 4
    for (int ic = 0; ic < C; ic++) {
        float2 xv = *(const float2*)&xs[ic][ty * 2];
        float w0 = ws[tx][ic];
        float w1 = ws[tx + 16][ic];
        float w2 = ws[tx + 32][ic];
        float w3 = ws[tx + 48][ic];
        acc[0][0] += xv.x * w0;  acc[1][0] += xv.y * w0;
        acc[0][1] += xv.x * w1;  acc[1][1] += xv.y * w1;
        acc[0][2] += xv.x * w2;  acc[1][2] += xv.y * w2;
        acc[0][3] += xv.x * w3;  acc[1][3] += xv.y * w3;
    }

#pragma unroll
    for (int i = 0; i < 2; i++) {
        int node = node0 + ty * 2 + i;
        if (node < n) {
#pragma unroll
            for (int j = 0; j < 4; j++) {
                int oc = tx + j * 16;
                float v = acc[i][j] + bs[oc];
                out[(size_t)node * OC + oc] = 1.0f / (1.0f + __expf(-v));
            }
        }
    }
}

// ---------------------------------------------------------------- launch
extern "C" void kernel_launch(void* const* d_in, const int* in_sizes, int n_in,
                              void* d_out, int out_size) {
    const float* x  = (const float*)d_in[0];
    const int*   ei = (const int*)d_in[1];
    const float* Wm = (const float*)d_in[2];
    const float* b  = (const float*)d_in[3];
    float* out = (float*)d_out;

    int n = in_sizes[0] / C;   // 100000
    int e = in_sizes[1] / 2;   // 800000
    int nb = (n + SCAN_B - 1) / SCAN_B;

    k_init<<<(n + 255) / 256, 256>>>(n);
    k_hist<<<(e + 255) / 256, 256>>>(ei, e);
    k_scan_blocks<<<nb, SCAN_B>>>(n);
    k_scan_sums<<<1, 32>>>(nb);
    k_scan_fixup<<<(n + 255) / 256, 256>>>(n);
    k_fill<<<(e + 255) / 256, 256>>>(ei, e);

    // 8 warps (8 nodes) per 256-thread block
    int hop_blocks = (n + 7) / 8;
    k_hop<<<hop_blocks, 256>>>(x, 0, n);
    k_hop<<<hop_blocks, 256>>>(x, 1, n);

    k_gemm_sig<<<(n + 31) / 32, 256>>>(Wm, b, out, n);
}